// round 3
// baseline (speedup 1.0000x reference)
#include <cuda_runtime.h>
#include <stdint.h>

// ---------------------------------------------------------------------------
// BoltzmannGateSTE: keep top-k (k = int(n/e)) elements by |x|, zero the rest.
// Exact k-th |x| via 2-level radix select on abs bit patterns.
//   pass A: coarse hist of top 12 abs bits (read 128 MB)
//   pass B (FUSED): write decided outputs, compact boundary-bucket elems
//           to a side list (read 128 MB + write 128 MB + ~6 MB list)
//   small:  fine hist built FROM THE LIST (~6 MB), scans, fixup (~9 MB)
// ---------------------------------------------------------------------------

#define NCOARSE 4096
#define NFINE   (1 << 19)
#define NSUPER  512
#define LISTCAP (1 << 22)   // 4M entries (expected ~710K)
#define CAPB    2048        // per-block staging (expected ~700/block)

__device__ unsigned g_coarse[NCOARSE];
__device__ unsigned g_fine[NFINE];
__device__ unsigned g_super[NSUPER];
__device__ unsigned g_bucket;   // coarse boundary bucket b*
__device__ unsigned g_krem;     // residual rank inside b*
__device__ unsigned g_tbits;    // exact abs-bits of k-th largest |x|
__device__ unsigned g_listcnt;
__device__ unsigned g_overflow;
__device__ uint2    g_list[LISTCAP];   // {element index, raw float bits}

// ---------------- zero scratch (runs each replay) --------------------------
__global__ void zero_hists() {
    int idx = blockIdx.x * blockDim.x + threadIdx.x;
    int stride = gridDim.x * blockDim.x;
    for (int i = idx; i < NFINE; i += stride) g_fine[i] = 0;
    for (int i = idx; i < NCOARSE; i += stride) g_coarse[i] = 0;
    if (idx == 0) { g_listcnt = 0; g_overflow = 0; }
}

// ---------------- pass A: coarse histogram (top 12 abs bits) ---------------
__global__ void coarse_hist(const float4* __restrict__ x, int n4) {
    __shared__ unsigned sh[NCOARSE];
    for (int i = threadIdx.x; i < NCOARSE; i += blockDim.x) sh[i] = 0;
    __syncthreads();
    int idx = blockIdx.x * blockDim.x + threadIdx.x;
    int stride = gridDim.x * blockDim.x;
#define H(f) atomicAdd(&sh[(__float_as_uint(f) & 0x7FFFFFFFu) >> 19], 1u)
    int i = idx;
    for (; i + 3 * stride < n4; i += 4 * stride) {
        float4 v0 = __ldcs(&x[i]);
        float4 v1 = __ldcs(&x[i + stride]);
        float4 v2 = __ldcs(&x[i + 2 * stride]);
        float4 v3 = __ldcs(&x[i + 3 * stride]);
        H(v0.x); H(v0.y); H(v0.z); H(v0.w);
        H(v1.x); H(v1.y); H(v1.z); H(v1.w);
        H(v2.x); H(v2.y); H(v2.z); H(v2.w);
        H(v3.x); H(v3.y); H(v3.z); H(v3.w);
    }
    for (; i < n4; i += stride) {
        float4 v = __ldcs(&x[i]);
        H(v.x); H(v.y); H(v.z); H(v.w);
    }
#undef H
    __syncthreads();
    for (int j = threadIdx.x; j < NCOARSE; j += blockDim.x) {
        unsigned c = sh[j];
        if (c) atomicAdd(&g_coarse[j], c);
    }
}

// ---------------- scan coarse hist from top; find boundary bucket ----------
__global__ void coarse_scan(unsigned k) {
    __shared__ unsigned s[1024];
    const int t = threadIdx.x;
    unsigned c0 = g_coarse[4 * t + 0];
    unsigned c1 = g_coarse[4 * t + 1];
    unsigned c2 = g_coarse[4 * t + 2];
    unsigned c3 = g_coarse[4 * t + 3];
    s[t] = c0 + c1 + c2 + c3;
    __syncthreads();
    for (int off = 1; off < 1024; off <<= 1) {
        unsigned add = (t + off < 1024) ? s[t + off] : 0u;
        __syncthreads();
        s[t] += add;
        __syncthreads();
    }
    unsigned above = (t < 1023) ? s[t + 1] : 0u;
    unsigned cum3 = above + c3;
    unsigned cum2 = cum3 + c2;
    unsigned cum1 = cum2 + c1;
    unsigned cum0 = cum1 + c0;
    if (cum3 >= k && above < k) { g_bucket = 4u * t + 3u; g_krem = k - above; }
    if (cum2 >= k && cum3  < k) { g_bucket = 4u * t + 2u; g_krem = k - cum3;  }
    if (cum1 >= k && cum2  < k) { g_bucket = 4u * t + 1u; g_krem = k - cum2;  }
    if (cum0 >= k && cum1  < k) { g_bucket = 4u * t + 0u; g_krem = k - cum1;  }
}

// ---------------- pass B: fused decided-output + boundary compaction -------
// Hot loop is pure: and/cmp/sel + rare predicated smem push. No ballots,
// no fine-hist atomics (fine hist is rebuilt from the list afterwards).
__global__ void fused_pass(const float4* __restrict__ x, float4* __restrict__ out, int n4) {
    __shared__ uint2 buf[CAPB];
    __shared__ unsigned scnt, sbase;
    if (threadIdx.x == 0) scnt = 0;
    __syncthreads();
    const unsigned b  = g_bucket;
    const unsigned hi = (b + 1u) << 19;   // keep iff abs-bits >= hi
    int idx = blockIdx.x * blockDim.x + threadIdx.x;
    int stride = gridDim.x * blockDim.x;

#define DO1(f, eidx, odst) { \
    unsigned raw = __float_as_uint(f); \
    unsigned u = raw & 0x7FFFFFFFu; \
    odst = (u >= hi) ? f : 0.0f; \
    if ((u >> 19) == b) { \
        unsigned pos = atomicAdd(&scnt, 1u); \
        if (pos < CAPB) { buf[pos].x = (eidx); buf[pos].y = raw; } \
    } \
}
#define DO4(vv, fi) { \
    float4 o; \
    unsigned eb = (unsigned)(fi) * 4u; \
    DO1(vv.x, eb + 0u, o.x); \
    DO1(vv.y, eb + 1u, o.y); \
    DO1(vv.z, eb + 2u, o.z); \
    DO1(vv.w, eb + 3u, o.w); \
    __stcs(&out[fi], o); \
}

    int i = idx;
    for (; i + stride < n4; i += 2 * stride) {
        float4 v0 = __ldcs(&x[i]);
        float4 v1 = __ldcs(&x[i + stride]);
        DO4(v0, i);
        DO4(v1, i + stride);
    }
    for (; i < n4; i += stride) {
        float4 v = __ldcs(&x[i]);
        DO4(v, i);
    }
#undef DO4
#undef DO1

    // flush staging buffer to global list
    __syncthreads();
    if (threadIdx.x == 0) {
        unsigned c = scnt;
        if (c > CAPB) { c = CAPB; g_overflow = 1; }
        sbase = atomicAdd(&g_listcnt, c);
        if (sbase + c > LISTCAP) g_overflow = 1;
    }
    __syncthreads();
    unsigned c = scnt; if (c > CAPB) c = CAPB;
    unsigned base = sbase;
    for (unsigned j = threadIdx.x; j < c; j += blockDim.x) {
        if (base + j < LISTCAP) g_list[base + j] = buf[j];
    }
}

// ---------------- fine histogram: from list (fast) or full rescan ----------
__global__ void fine_hist_k(const float4* __restrict__ x, int n4) {
    int idx = blockIdx.x * blockDim.x + threadIdx.x;
    int stride = gridDim.x * blockDim.x;
    if (!g_overflow) {
        unsigned cnt = g_listcnt;
        if (cnt > LISTCAP) cnt = LISTCAP;
        for (unsigned j = idx; j < cnt; j += stride) {
            unsigned u = g_list[j].y & 0x7FFFFFFFu;
            atomicAdd(&g_fine[u & 0x7FFFFu], 1u);
        }
    } else {
        const unsigned b = g_bucket;
        for (int i = idx; i < n4; i += stride) {
            float4 v = x[i];
            unsigned ux = __float_as_uint(v.x) & 0x7FFFFFFFu;
            unsigned uy = __float_as_uint(v.y) & 0x7FFFFFFFu;
            unsigned uz = __float_as_uint(v.z) & 0x7FFFFFFFu;
            unsigned uw = __float_as_uint(v.w) & 0x7FFFFFFFu;
            if ((ux >> 19) == b) atomicAdd(&g_fine[ux & 0x7FFFFu], 1u);
            if ((uy >> 19) == b) atomicAdd(&g_fine[uy & 0x7FFFFu], 1u);
            if ((uz >> 19) == b) atomicAdd(&g_fine[uz & 0x7FFFFu], 1u);
            if ((uw >> 19) == b) atomicAdd(&g_fine[uw & 0x7FFFFu], 1u);
        }
    }
}

// ---------------- reduce fine hist into 512 super-buckets ------------------
__global__ void fine_super() {
    __shared__ unsigned red[256];
    int base = blockIdx.x * 1024 + threadIdx.x * 4;
    unsigned v = g_fine[base] + g_fine[base + 1] + g_fine[base + 2] + g_fine[base + 3];
    red[threadIdx.x] = v;
    __syncthreads();
    for (int off = 128; off > 0; off >>= 1) {
        if (threadIdx.x < off) red[threadIdx.x] += red[threadIdx.x + off];
        __syncthreads();
    }
    if (threadIdx.x == 0) g_super[blockIdx.x] = red[0];
}

// ---------------- final scan: exact threshold bits -------------------------
__global__ void fine_scan() {
    __shared__ unsigned s[1024];
    __shared__ unsigned sh_super, sh_krem2;
    const int t = threadIdx.x;
    const unsigned krem = g_krem;

    s[t] = (t < NSUPER) ? g_super[t] : 0u;
    __syncthreads();
    for (int off = 1; off < 1024; off <<= 1) {
        unsigned add = (t + off < 1024) ? s[t + off] : 0u;
        __syncthreads();
        s[t] += add;
        __syncthreads();
    }
    if (t < NSUPER) {
        unsigned cum  = s[t];
        unsigned next = (t + 1 < NSUPER) ? s[t + 1] : 0u;
        if (cum >= krem && next < krem) { sh_super = (unsigned)t; sh_krem2 = krem - next; }
    }
    __syncthreads();
    const unsigned sb = sh_super;
    const unsigned krem2 = sh_krem2;

    unsigned cfine = g_fine[sb * 1024 + t];
    __syncthreads();
    s[t] = cfine;
    __syncthreads();
    for (int off = 1; off < 1024; off <<= 1) {
        unsigned add = (t + off < 1024) ? s[t + off] : 0u;
        __syncthreads();
        s[t] += add;
        __syncthreads();
    }
    {
        unsigned cum  = s[t];
        unsigned next = (t < 1023) ? s[t + 1] : 0u;
        if (cum >= krem2 && next < krem2) {
            g_tbits = (g_bucket << 19) | (sb * 1024u + (unsigned)t);
        }
    }
}

// ---------------- fixup: scatter-write boundary keepers from list ----------
__global__ void fixup(float* __restrict__ out) {
    if (g_overflow) return;   // fallback kernel handles this case
    const unsigned tb = g_tbits;
    unsigned cnt = g_listcnt;
    if (cnt > LISTCAP) cnt = LISTCAP;
    unsigned idx = blockIdx.x * blockDim.x + threadIdx.x;
    unsigned stride = gridDim.x * blockDim.x;
    for (unsigned j = idx; j < cnt; j += stride) {
        uint2 e = g_list[j];
        if ((e.y & 0x7FFFFFFFu) >= tb) out[e.x] = __uint_as_float(e.y);
    }
}

// ---------------- fallback: full re-mask if staging overflowed -------------
__global__ void fallback_mask(const float4* __restrict__ x, float4* __restrict__ out, int n4) {
    if (!g_overflow) return;
    const unsigned tb = g_tbits;
    int idx = blockIdx.x * blockDim.x + threadIdx.x;
    int stride = gridDim.x * blockDim.x;
    for (int i = idx; i < n4; i += stride) {
        float4 v = x[i];
        v.x = ((__float_as_uint(v.x) & 0x7FFFFFFFu) >= tb) ? v.x : 0.0f;
        v.y = ((__float_as_uint(v.y) & 0x7FFFFFFFu) >= tb) ? v.y : 0.0f;
        v.z = ((__float_as_uint(v.z) & 0x7FFFFFFFu) >= tb) ? v.z : 0.0f;
        v.w = ((__float_as_uint(v.w) & 0x7FFFFFFFu) >= tb) ? v.w : 0.0f;
        out[i] = v;
    }
}

__global__ void copy_all(const float4* __restrict__ x, float4* __restrict__ out, int n4) {
    int idx = blockIdx.x * blockDim.x + threadIdx.x;
    int stride = gridDim.x * blockDim.x;
    for (int i = idx; i < n4; i += stride) out[i] = x[i];
}

extern "C" void kernel_launch(void* const* d_in, const int* in_sizes, int n_in,
                              void* d_out, int out_size) {
    const float* x = (const float*)d_in[0];
    float* out = (float*)d_out;
    int n = in_sizes[0];

    // k = max(1, int(n * (1.0/e))) — bit-exact replication of the Python.
    const double FRACTION = 1.0 / 2.718281828459045235360287;
    long long kll = (long long)((double)n * FRACTION);
    if (kll < 1) kll = 1;

    int n4 = n / 4;             // n = 33,554,432
    const int BLK = 256;
    const int GRID = 1024;      // 2^18 threads -> even division of n4 = 2^23

    if (kll >= (long long)n) {
        copy_all<<<GRID, BLK>>>((const float4*)x, (float4*)out, n4);
        return;
    }
    unsigned k = (unsigned)kll;

    zero_hists<<<512, 256>>>();
    coarse_hist<<<GRID, BLK>>>((const float4*)x, n4);
    coarse_scan<<<1, 1024>>>(k);
    fused_pass<<<GRID, BLK>>>((const float4*)x, (float4*)out, n4);
    fine_hist_k<<<GRID, BLK>>>((const float4*)x, n4);
    fine_super<<<NSUPER, 256>>>();
    fine_scan<<<1, 1024>>>();
    fixup<<<512, 256>>>(out);
    fallback_mask<<<GRID, BLK>>>((const float4*)x, (float4*)out, n4);
}

// round 4
// speedup vs baseline: 1.1854x; 1.1854x over previous
#include <cuda_runtime.h>
#include <stdint.h>

// ---------------------------------------------------------------------------
// BoltzmannGateSTE: keep top-k (k = int(n/e)) by |x|, zero the rest.
// SINGLE persistent kernel, software grid barriers between phases:
//  P1: coarse hist (top 12 abs bits) in smem, merge to global   [read 128MB]
//  P2: block0 scans coarse hist -> boundary bucket b*, residual rank;
//      other 443 blocks zero the 2MB fine histogram concurrently
//  P3: fused: write decided outputs, stage boundary elems in smem, flush to
//      global list AND build fine hist from staged entries  [r128+w128+~6MB]
//  P4: reduce fine hist to 512 supers (all blocks); block0 scans -> exact
//      threshold bits
//  P5: fixup boundary keepers from list (~9MB); cleanup scratch for replay
// Overflow of any staging buffer -> exact fallback path (rebuild fine hist
// from x, full re-mask). Even number of grid barriers on every path so the
// barrier sense flag returns to 0 for the next graph replay.
// ---------------------------------------------------------------------------

#define NCOARSE 4096
#define NFINE   (1 << 19)
#define NSUPER  512
#define LISTCAP (1 << 22)   // 4M entries (expected ~560K)
#define CAPB    3840        // per-block staging (expected ~1255/block)
#define NBLK    444         // 148 SMs * 3 co-resident blocks
#define NTHR    512
#define NTOT    (NBLK * NTHR)
#define WND     (1u << 19)

__device__ unsigned g_coarse[NCOARSE];
__device__ unsigned g_fine[NFINE];
__device__ unsigned g_super[NSUPER];
__device__ unsigned g_bucket;
__device__ unsigned g_krem;
__device__ unsigned g_tbits;
__device__ unsigned g_listcnt;
__device__ unsigned g_overflow;
__device__ unsigned g_bar_cnt;
__device__ volatile unsigned g_bar_sense;
__device__ uint2    g_list[LISTCAP];

// -------- software grid barrier (sense-reversing) --------------------------
__device__ __forceinline__ void gbar(unsigned* sense_smem) {
    __syncthreads();
    if (threadIdx.x == 0) {
        unsigned s = *sense_smem ^ 1u;
        *sense_smem = s;
        __threadfence();
        if (atomicAdd(&g_bar_cnt, 1u) == NBLK - 1u) {
            g_bar_cnt = 0u;
            __threadfence();
            g_bar_sense = s;
        } else {
            while (g_bar_sense != s) __nanosleep(64);
            __threadfence();
        }
    }
    __syncthreads();
}

__global__ void __launch_bounds__(NTHR, 3)
boltzmann_all(const float4* __restrict__ x, float4* __restrict__ out,
              int n4, int rem, unsigned k)
{
    __shared__ unsigned shist[NCOARSE];   // 16KB: hist / scan scratch
    __shared__ uint2    sbuf[CAPB];       // 30KB: boundary staging
    __shared__ unsigned svar[8];          // 0:scnt 1:sbase 2:sense 3:sb 4:krem2

    const int tid  = threadIdx.x;
    const int gtid = blockIdx.x * NTHR + tid;
    const float* xs = (const float*)x;

    if (tid < 8) svar[tid] = 0;           // sense=0, scnt=0, ...

    // ======================= P1: coarse histogram ==========================
    for (int i = tid; i < NCOARSE; i += NTHR) shist[i] = 0;
    __syncthreads();
#define H(f) atomicAdd(&shist[(__float_as_uint(f) & 0x7FFFFFFFu) >> 19], 1u)
    {
        int i = gtid;
        for (; i + 3 * NTOT < n4; i += 4 * NTOT) {
            float4 v0 = __ldcs(&x[i]);
            float4 v1 = __ldcs(&x[i + NTOT]);
            float4 v2 = __ldcs(&x[i + 2 * NTOT]);
            float4 v3 = __ldcs(&x[i + 3 * NTOT]);
            H(v0.x); H(v0.y); H(v0.z); H(v0.w);
            H(v1.x); H(v1.y); H(v1.z); H(v1.w);
            H(v2.x); H(v2.y); H(v2.z); H(v2.w);
            H(v3.x); H(v3.y); H(v3.z); H(v3.w);
        }
        for (; i < n4; i += NTOT) {
            float4 v = __ldcs(&x[i]);
            H(v.x); H(v.y); H(v.z); H(v.w);
        }
    }
#undef H
    __syncthreads();
    for (int i = tid; i < NCOARSE; i += NTHR) {
        unsigned c = shist[i];
        if (c) atomicAdd(&g_coarse[i], c);
    }
    if (gtid < rem) {   // scalar tail (empty for this shape)
        unsigned u = __float_as_uint(xs[n4 * 4 + gtid]) & 0x7FFFFFFFu;
        atomicAdd(&g_coarse[u >> 19], 1u);
    }
    gbar(&svar[2]);   // ---- barrier 1

    // ====== P2: block0 scans coarse; others zero fine hist =================
    if (blockIdx.x == 0) {
        unsigned c[8], sum = 0;
        #pragma unroll
        for (int j = 0; j < 8; j++) { c[j] = g_coarse[tid * 8 + j]; sum += c[j]; }
        shist[tid] = sum;
        __syncthreads();
        for (int off = 1; off < NTHR; off <<= 1) {
            unsigned add = (tid + off < NTHR) ? shist[tid + off] : 0u;
            __syncthreads();
            shist[tid] += add;
            __syncthreads();
        }
        unsigned cum = (tid < NTHR - 1) ? shist[tid + 1] : 0u;  // suffix above
        #pragma unroll
        for (int j = 7; j >= 0; j--) {
            unsigned prev = cum;
            cum += c[j];
            if (cum >= k && prev < k) {
                g_bucket = (unsigned)(tid * 8 + j);
                g_krem   = k - prev;
            }
        }
    } else {
        int idx = (blockIdx.x - 1) * NTHR + tid;
        for (int i = idx; i < NFINE; i += (NBLK - 1) * NTHR) g_fine[i] = 0;
    }
    gbar(&svar[2]);   // ---- barrier 2

    // ======================= P3: fused mask + compact ======================
    const unsigned b  = g_bucket;
    const unsigned lo = b << 19;
    const unsigned hi = lo + WND;
    if (tid == 0) svar[0] = 0;
    __syncthreads();

#define BODY(i_) { \
    float4 v = __ldcs(&x[i_]); \
    unsigned r0 = __float_as_uint(v.x), r1 = __float_as_uint(v.y); \
    unsigned r2 = __float_as_uint(v.z), r3 = __float_as_uint(v.w); \
    unsigned u0 = r0 & 0x7FFFFFFFu, u1 = r1 & 0x7FFFFFFFu; \
    unsigned u2 = r2 & 0x7FFFFFFFu, u3 = r3 & 0x7FFFFFFFu; \
    float4 o; \
    o.x = (u0 >= hi) ? v.x : 0.0f; \
    o.y = (u1 >= hi) ? v.y : 0.0f; \
    o.z = (u2 >= hi) ? v.z : 0.0f; \
    o.w = (u3 >= hi) ? v.w : 0.0f; \
    __stcs(&out[i_], o); \
    unsigned d0 = u0 - lo, d1 = u1 - lo, d2 = u2 - lo, d3 = u3 - lo; \
    if ((d0 < WND) | (d1 < WND) | (d2 < WND) | (d3 < WND)) { \
        unsigned eb = (unsigned)(i_) * 4u; \
        if (d0 < WND) { unsigned p = atomicAdd(&svar[0], 1u); if (p < CAPB) { sbuf[p].x = eb;      sbuf[p].y = r0; } } \
        if (d1 < WND) { unsigned p = atomicAdd(&svar[0], 1u); if (p < CAPB) { sbuf[p].x = eb + 1u; sbuf[p].y = r1; } } \
        if (d2 < WND) { unsigned p = atomicAdd(&svar[0], 1u); if (p < CAPB) { sbuf[p].x = eb + 2u; sbuf[p].y = r2; } } \
        if (d3 < WND) { unsigned p = atomicAdd(&svar[0], 1u); if (p < CAPB) { sbuf[p].x = eb + 3u; sbuf[p].y = r3; } } \
    } \
}
    {
        int i = gtid;
        for (; i + NTOT < n4; i += 2 * NTOT) { BODY(i); BODY(i + NTOT); }
        for (; i < n4; i += NTOT) BODY(i);
    }
#undef BODY
    if (gtid < rem) {   // scalar tail
        float f = xs[n4 * 4 + gtid];
        unsigned raw = __float_as_uint(f);
        unsigned u = raw & 0x7FFFFFFFu;
        ((float*)out)[n4 * 4 + gtid] = (u >= hi) ? f : 0.0f;
        if (u - lo < WND) {
            unsigned p = atomicAdd(&svar[0], 1u);
            if (p < CAPB) { sbuf[p].x = (unsigned)(n4 * 4 + gtid); sbuf[p].y = raw; }
        }
    }
    // flush staging: list + fine hist from staged entries
    __syncthreads();
    if (tid == 0) {
        unsigned c = svar[0];
        if (c > CAPB) { c = CAPB; g_overflow = 1u; }
        unsigned base = atomicAdd(&g_listcnt, c);
        if (base + c > LISTCAP) g_overflow = 1u;
        svar[0] = c;
        svar[1] = base;
    }
    __syncthreads();
    {
        unsigned c = svar[0], base = svar[1];
        for (unsigned j = tid; j < c; j += NTHR) {
            uint2 e = sbuf[j];
            if (base + j < LISTCAP) g_list[base + j] = e;
            atomicAdd(&g_fine[e.y & 0x7FFFFu], 1u);
        }
    }
    gbar(&svar[2]);   // ---- barrier 3

    const unsigned ovf = g_overflow;
    unsigned cnt = g_listcnt;
    if (cnt > LISTCAP) cnt = LISTCAP;

    if (ovf) {   // exact fallback: rebuild fine hist from x (adds 2 barriers)
        for (int i = gtid; i < NFINE; i += NTOT) g_fine[i] = 0;
        gbar(&svar[2]);
        for (int i = gtid; i < n4; i += NTOT) {
            float4 v = x[i];
            unsigned u0 = __float_as_uint(v.x) & 0x7FFFFFFFu;
            unsigned u1 = __float_as_uint(v.y) & 0x7FFFFFFFu;
            unsigned u2 = __float_as_uint(v.z) & 0x7FFFFFFFu;
            unsigned u3 = __float_as_uint(v.w) & 0x7FFFFFFFu;
            if (u0 - lo < WND) atomicAdd(&g_fine[u0 & 0x7FFFFu], 1u);
            if (u1 - lo < WND) atomicAdd(&g_fine[u1 & 0x7FFFFu], 1u);
            if (u2 - lo < WND) atomicAdd(&g_fine[u2 & 0x7FFFFu], 1u);
            if (u3 - lo < WND) atomicAdd(&g_fine[u3 & 0x7FFFFu], 1u);
        }
        for (int g = gtid; g < rem; g += NTOT) {
            unsigned u = __float_as_uint(xs[n4 * 4 + g]) & 0x7FFFFFFFu;
            if (u - lo < WND) atomicAdd(&g_fine[u & 0x7FFFFu], 1u);
        }
        gbar(&svar[2]);
    }

    // ======== P4a: reduce fine hist -> 512 super sums (all blocks) =========
    for (int s = blockIdx.x; s < NSUPER; s += NBLK) {
        unsigned v = g_fine[s * 1024 + tid] + g_fine[s * 1024 + tid + NTHR];
        shist[tid] = v;
        __syncthreads();
        for (int off = NTHR / 2; off > 0; off >>= 1) {
            if (tid < off) shist[tid] += shist[tid + off];
            __syncthreads();
        }
        if (tid == 0) g_super[s] = shist[0];
        __syncthreads();
    }
    gbar(&svar[2]);   // ---- barrier 4

    // ======== P4b: block0 scans supers + fine bucket -> exact tbits ========
    if (blockIdx.x == 0) {
        const unsigned krem = g_krem;
        shist[tid] = g_super[tid];
        __syncthreads();
        for (int off = 1; off < NTHR; off <<= 1) {
            unsigned add = (tid + off < NTHR) ? shist[tid + off] : 0u;
            __syncthreads();
            shist[tid] += add;
            __syncthreads();
        }
        {
            unsigned cum  = shist[tid];
            unsigned next = (tid < NTHR - 1) ? shist[tid + 1] : 0u;
            if (cum >= krem && next < krem) { svar[3] = (unsigned)tid; svar[4] = krem - next; }
        }
        __syncthreads();
        const unsigned sb = svar[3], krem2 = svar[4];
        unsigned c0 = g_fine[sb * 1024 + 2 * tid];
        unsigned c1 = g_fine[sb * 1024 + 2 * tid + 1];
        __syncthreads();
        shist[tid] = c0 + c1;
        __syncthreads();
        for (int off = 1; off < NTHR; off <<= 1) {
            unsigned add = (tid + off < NTHR) ? shist[tid + off] : 0u;
            __syncthreads();
            shist[tid] += add;
            __syncthreads();
        }
        {
            unsigned above = (tid < NTHR - 1) ? shist[tid + 1] : 0u;
            unsigned cum1 = above + c1;
            unsigned cum0 = cum1 + c0;
            if (cum1 >= krem2 && above < krem2)
                g_tbits = lo | (sb * 1024u + 2u * tid + 1u);
            if (cum0 >= krem2 && cum1 < krem2)
                g_tbits = lo | (sb * 1024u + 2u * tid);
        }
    }
    gbar(&svar[2]);   // ---- barrier 5

    // ======================= P5: fixup / fallback ==========================
    const unsigned tb = g_tbits;
    if (!ovf) {
        for (unsigned j = (unsigned)gtid; j < cnt; j += NTOT) {
            uint2 e = g_list[j];
            if ((e.y & 0x7FFFFFFFu) >= tb) ((float*)out)[e.x] = __uint_as_float(e.y);
        }
    } else {
        for (int i = gtid; i < n4; i += NTOT) {
            float4 v = x[i];
            v.x = ((__float_as_uint(v.x) & 0x7FFFFFFFu) >= tb) ? v.x : 0.0f;
            v.y = ((__float_as_uint(v.y) & 0x7FFFFFFFu) >= tb) ? v.y : 0.0f;
            v.z = ((__float_as_uint(v.z) & 0x7FFFFFFFu) >= tb) ? v.z : 0.0f;
            v.w = ((__float_as_uint(v.w) & 0x7FFFFFFFu) >= tb) ? v.w : 0.0f;
            out[i] = v;
        }
        for (int g = gtid; g < rem; g += NTOT) {
            float f = xs[n4 * 4 + g];
            ((float*)out)[n4 * 4 + g] =
                ((__float_as_uint(f) & 0x7FFFFFFFu) >= tb) ? f : 0.0f;
        }
    }
    gbar(&svar[2]);   // ---- barrier 6 (even count; sense back to 0)

    // cleanup scratch for the next graph replay
    for (int i = gtid; i < NCOARSE; i += NTOT) g_coarse[i] = 0;
    if (gtid == 0) { g_listcnt = 0; g_overflow = 0; }
}

__global__ void copy_all(const float4* __restrict__ x, float4* __restrict__ out, int n4) {
    int idx = blockIdx.x * blockDim.x + threadIdx.x;
    int stride = gridDim.x * blockDim.x;
    for (int i = idx; i < n4; i += stride) out[i] = x[i];
}

extern "C" void kernel_launch(void* const* d_in, const int* in_sizes, int n_in,
                              void* d_out, int out_size) {
    const float* x = (const float*)d_in[0];
    float* out = (float*)d_out;
    int n = in_sizes[0];

    // k = max(1, int(n * (1.0/e))) — bit-exact replication of the Python.
    const double FRACTION = 1.0 / 2.718281828459045235360287;
    long long kll = (long long)((double)n * FRACTION);
    if (kll < 1) kll = 1;

    int n4 = n >> 2;
    int rem = n & 3;

    if (kll >= (long long)n) {
        copy_all<<<1024, 256>>>((const float4*)x, (float4*)out, n4);
        return;
    }

    boltzmann_all<<<NBLK, NTHR>>>((const float4*)x, (float4*)out,
                                  n4, rem, (unsigned)kll);
}

// round 5
// speedup vs baseline: 1.3902x; 1.1727x over previous
#include <cuda_runtime.h>
#include <stdint.h>

// ---------------------------------------------------------------------------
// BoltzmannGateSTE: keep top-k (k = int(n/e)) by |x|, zero the rest.
// ONE streamed pass with a speculative threshold window + exact verification:
//  P1: read x once -> write out speculatively (keep iff |x|bits >= WHI),
//      count A = #{bits >= WHI} (register counters), stage window elements
//      (bits in [WLO, WHI)) to a global list AND into a 2^20-bin exact hist.
//  P2: verify: !overflow && A < k && k-A <= listcnt  => threshold inside
//      window, resolvable bit-exactly from the histogram.
//  P4: reduce hist -> 1024 supers; block0 double-scan -> exact tbits.
//  P5: fixup only listed elements.
//  Fallback (verification fails, any input distribution): full exact radix
//  select (coarse hist -> fine hist -> re-mask) inside the same kernel.
// Prologue kernel zeroes all scratch + barrier state each replay.
// ---------------------------------------------------------------------------

#define NBINS   (1u << 20)
#define NSUP    1024
#define NCOARSE 4096
#define LISTCAP (1 << 22)      // 4M entries (expected ~1.11M)
#define CAPB    3584           // per-block staging (expected ~2500)
#define NBLK    444            // 148 SMs * 3 (co-residency proven in R4)
#define NTHR    512
#define NTOT    (NBLK * NTHR)
#define WLO_N   0x3F600000u    // bits(0.875f)
#define WSPAN_N (1u << 20)     // window = exactly 2^20 ulp-groups
#define WHI_N   (WLO_N + WSPAN_N)   // bits(0.9375f)

__device__ __align__(16) unsigned g_fine[NBINS];
__device__ unsigned g_super[NSUP];
__device__ unsigned g_coarse[NCOARSE];
__device__ unsigned g_A;
__device__ unsigned g_listcnt;
__device__ unsigned g_overflow;
__device__ unsigned g_mode;
__device__ unsigned g_krem;
__device__ unsigned g_wlo;
__device__ unsigned g_tbits;
__device__ unsigned g_bar_cnt;
__device__ volatile unsigned g_bar_sense;
__device__ uint2    g_list[LISTCAP];

// -------- prologue: zero ALL scratch + barrier state (runs each replay) ----
__global__ void zero_all() {
    int idx = blockIdx.x * blockDim.x + threadIdx.x;
    int stride = gridDim.x * blockDim.x;
    for (unsigned i = idx; i < NBINS; i += stride) g_fine[i] = 0;
    for (int i = idx; i < NCOARSE; i += stride) g_coarse[i] = 0;
    for (int i = idx; i < NSUP; i += stride) g_super[i] = 0;
    if (idx == 0) {
        g_A = 0; g_listcnt = 0; g_overflow = 0; g_mode = 0;
        g_bar_cnt = 0; g_bar_sense = 0;
    }
}

// -------- software grid barrier (sense-reversing; state reset by prologue) -
__device__ __forceinline__ void gbar(unsigned* sense_smem) {
    __syncthreads();
    if (threadIdx.x == 0) {
        unsigned s = *sense_smem ^ 1u;
        *sense_smem = s;
        __threadfence();
        if (atomicAdd(&g_bar_cnt, 1u) == NBLK - 1u) {
            g_bar_cnt = 0u;
            __threadfence();
            g_bar_sense = s;
        } else {
            while (g_bar_sense != s) __nanosleep(64);
            __threadfence();
        }
    }
    __syncthreads();
}

// -------- block0: double suffix-scan of 1024 supers then 1024 bins ---------
__device__ void final_scan(unsigned* scratch, unsigned* svar) {
    const int t = threadIdx.x;
    const unsigned krem = g_krem;
    const unsigned wlo  = g_wlo;

    // scan supers (1024 entries, 2 per thread)
    unsigned e0 = g_super[2 * t], e1 = g_super[2 * t + 1];
    scratch[t] = e0 + e1;
    __syncthreads();
    for (int off = 1; off < NTHR; off <<= 1) {
        unsigned add = (t + off < NTHR) ? scratch[t + off] : 0u;
        __syncthreads();
        scratch[t] += add;
        __syncthreads();
    }
    {
        unsigned above = (t < NTHR - 1) ? scratch[t + 1] : 0u;
        unsigned cum1 = above + e1;
        unsigned cum0 = cum1 + e0;
        if (cum1 >= krem && above < krem) { svar[3] = 2u * t + 1u; svar[4] = krem - above; }
        if (cum0 >= krem && cum1  < krem) { svar[3] = 2u * t;      svar[4] = krem - cum1;  }
    }
    __syncthreads();
    const unsigned sb = svar[3], krem2 = svar[4];

    // scan the 1024 bins of super sb
    unsigned c0 = g_fine[sb * 1024 + 2 * t], c1 = g_fine[sb * 1024 + 2 * t + 1];
    __syncthreads();
    scratch[t] = c0 + c1;
    __syncthreads();
    for (int off = 1; off < NTHR; off <<= 1) {
        unsigned add = (t + off < NTHR) ? scratch[t + off] : 0u;
        __syncthreads();
        scratch[t] += add;
        __syncthreads();
    }
    {
        unsigned above = (t < NTHR - 1) ? scratch[t + 1] : 0u;
        unsigned cum1 = above + c1;
        unsigned cum0 = cum1 + c0;
        if (cum1 >= krem2 && above < krem2) g_tbits = wlo + sb * 1024u + 2u * t + 1u;
        if (cum0 >= krem2 && cum1  < krem2) g_tbits = wlo + sb * 1024u + 2u * t;
    }
}

__global__ void __launch_bounds__(NTHR, 3)
boltzmann_all(const float4* __restrict__ x, float4* __restrict__ out,
              int n4, int rem, unsigned k)
{
    __shared__ unsigned scratch[NCOARSE];  // 16KB: reductions / scans / hist
    __shared__ uint2    sbuf[CAPB];        // 28KB: boundary staging
    __shared__ unsigned svar[8];           // 0:scnt 1:sbase 2:sense 3:sb 4:krem2

    const int tid  = threadIdx.x;
    const int gtid = blockIdx.x * NTHR + tid;
    const float* xs = (const float*)x;
    float* outs = (float*)out;

    if (tid < 8) svar[tid] = 0;
    __syncthreads();

    // ============ P1: stream read -> speculative write + count + stage =====
    unsigned cntHi = 0;
#define BODY(i_) { \
    float4 v = __ldcs(&x[i_]); \
    unsigned r0 = __float_as_uint(v.x), r1 = __float_as_uint(v.y); \
    unsigned r2 = __float_as_uint(v.z), r3 = __float_as_uint(v.w); \
    unsigned u0 = r0 & 0x7FFFFFFFu, u1 = r1 & 0x7FFFFFFFu; \
    unsigned u2 = r2 & 0x7FFFFFFFu, u3 = r3 & 0x7FFFFFFFu; \
    float4 o; \
    o.x = (u0 >= WHI_N) ? v.x : 0.0f; \
    o.y = (u1 >= WHI_N) ? v.y : 0.0f; \
    o.z = (u2 >= WHI_N) ? v.z : 0.0f; \
    o.w = (u3 >= WHI_N) ? v.w : 0.0f; \
    cntHi += (u0 >= WHI_N) + (u1 >= WHI_N) + (u2 >= WHI_N) + (u3 >= WHI_N); \
    __stcs(&out[i_], o); \
    unsigned d0 = u0 - WLO_N, d1 = u1 - WLO_N, d2 = u2 - WLO_N, d3 = u3 - WLO_N; \
    if ((d0 < WSPAN_N) | (d1 < WSPAN_N) | (d2 < WSPAN_N) | (d3 < WSPAN_N)) { \
        unsigned eb = (unsigned)(i_) * 4u; \
        if (d0 < WSPAN_N) { unsigned p = atomicAdd(&svar[0], 1u); if (p < CAPB) { sbuf[p].x = eb;      sbuf[p].y = r0; } } \
        if (d1 < WSPAN_N) { unsigned p = atomicAdd(&svar[0], 1u); if (p < CAPB) { sbuf[p].x = eb + 1u; sbuf[p].y = r1; } } \
        if (d2 < WSPAN_N) { unsigned p = atomicAdd(&svar[0], 1u); if (p < CAPB) { sbuf[p].x = eb + 2u; sbuf[p].y = r2; } } \
        if (d3 < WSPAN_N) { unsigned p = atomicAdd(&svar[0], 1u); if (p < CAPB) { sbuf[p].x = eb + 3u; sbuf[p].y = r3; } } \
    } \
}
    {
        int i = gtid;
        for (; i + NTOT < n4; i += 2 * NTOT) { BODY(i); BODY(i + NTOT); }
        for (; i < n4; i += NTOT) BODY(i);
    }
#undef BODY
    if (gtid < rem) {   // scalar tail
        float f = xs[n4 * 4 + gtid];
        unsigned raw = __float_as_uint(f);
        unsigned u = raw & 0x7FFFFFFFu;
        cntHi += (u >= WHI_N);
        outs[n4 * 4 + gtid] = (u >= WHI_N) ? f : 0.0f;
        if (u - WLO_N < WSPAN_N) {
            unsigned p = atomicAdd(&svar[0], 1u);
            if (p < CAPB) { sbuf[p].x = (unsigned)(n4 * 4 + gtid); sbuf[p].y = raw; }
        }
    }

    // block-reduce cntHi -> g_A
    scratch[tid] = cntHi;
    __syncthreads();
    for (int off = NTHR / 2; off > 0; off >>= 1) {
        if (tid < off) scratch[tid] += scratch[tid + off];
        __syncthreads();
    }
    if (tid == 0) {
        if (scratch[0]) atomicAdd(&g_A, scratch[0]);
        unsigned c = svar[0];
        if (c > CAPB) { c = CAPB; g_overflow = 1u; }
        unsigned base = atomicAdd(&g_listcnt, c);
        if (base + c > LISTCAP) g_overflow = 1u;
        svar[0] = c;
        svar[1] = base;
    }
    __syncthreads();
    {   // flush staging -> list + window histogram
        unsigned c = svar[0], base = svar[1];
        for (unsigned j = tid; j < c; j += NTHR) {
            uint2 e = sbuf[j];
            if (base + j < LISTCAP) g_list[base + j] = e;
            atomicAdd(&g_fine[(e.y & 0x7FFFFFFFu) - WLO_N], 1u);
        }
    }
    gbar(&svar[2]);   // ---- barrier

    // ============ P2: exact verification ===================================
    if (blockIdx.x == 0 && tid == 0) {
        unsigned A = g_A, cnt = g_listcnt, ov = g_overflow;
        unsigned mode = 1u;
        if (!ov && A < k && (k - A) <= cnt) {
            mode = 0u; g_krem = k - A; g_wlo = WLO_N;
        }
        g_mode = mode;
    }
    gbar(&svar[2]);   // ---- barrier

    const unsigned mode = g_mode;
    unsigned cnt = g_listcnt;
    if (cnt > LISTCAP) cnt = LISTCAP;

    // ============ Fallback: full exact radix select ========================
    if (mode) {
        for (unsigned i = gtid; i < NBINS; i += NTOT) g_fine[i] = 0;
        for (int i = tid; i < NCOARSE; i += NTHR) scratch[i] = 0;
        __syncthreads();
        for (int i = gtid; i < n4; i += NTOT) {
            float4 v = x[i];
            atomicAdd(&scratch[(__float_as_uint(v.x) & 0x7FFFFFFFu) >> 19], 1u);
            atomicAdd(&scratch[(__float_as_uint(v.y) & 0x7FFFFFFFu) >> 19], 1u);
            atomicAdd(&scratch[(__float_as_uint(v.z) & 0x7FFFFFFFu) >> 19], 1u);
            atomicAdd(&scratch[(__float_as_uint(v.w) & 0x7FFFFFFFu) >> 19], 1u);
        }
        if (gtid < rem)
            atomicAdd(&scratch[(__float_as_uint(xs[n4 * 4 + gtid]) & 0x7FFFFFFFu) >> 19], 1u);
        __syncthreads();
        for (int i = tid; i < NCOARSE; i += NTHR) {
            unsigned c = scratch[i];
            if (c) atomicAdd(&g_coarse[i], c);
        }
        gbar(&svar[2]);

        if (blockIdx.x == 0) {   // coarse scan: 8 buckets per thread
            unsigned c[8], sum = 0;
            #pragma unroll
            for (int j = 0; j < 8; j++) { c[j] = g_coarse[tid * 8 + j]; sum += c[j]; }
            scratch[tid] = sum;
            __syncthreads();
            for (int off = 1; off < NTHR; off <<= 1) {
                unsigned add = (tid + off < NTHR) ? scratch[tid + off] : 0u;
                __syncthreads();
                scratch[tid] += add;
                __syncthreads();
            }
            unsigned cum = (tid < NTHR - 1) ? scratch[tid + 1] : 0u;
            #pragma unroll
            for (int j = 7; j >= 0; j--) {
                unsigned prev = cum;
                cum += c[j];
                if (cum >= k && prev < k) {
                    g_wlo  = ((unsigned)(tid * 8 + j)) << 19;
                    g_krem = k - prev;
                }
            }
        }
        gbar(&svar[2]);

        const unsigned wlo = g_wlo;
        for (int i = gtid; i < n4; i += NTOT) {
            float4 v = x[i];
            unsigned u0 = __float_as_uint(v.x) & 0x7FFFFFFFu;
            unsigned u1 = __float_as_uint(v.y) & 0x7FFFFFFFu;
            unsigned u2 = __float_as_uint(v.z) & 0x7FFFFFFFu;
            unsigned u3 = __float_as_uint(v.w) & 0x7FFFFFFFu;
            if (u0 - wlo < (1u << 19)) atomicAdd(&g_fine[u0 - wlo], 1u);
            if (u1 - wlo < (1u << 19)) atomicAdd(&g_fine[u1 - wlo], 1u);
            if (u2 - wlo < (1u << 19)) atomicAdd(&g_fine[u2 - wlo], 1u);
            if (u3 - wlo < (1u << 19)) atomicAdd(&g_fine[u3 - wlo], 1u);
        }
        if (gtid < rem) {
            unsigned u = __float_as_uint(xs[n4 * 4 + gtid]) & 0x7FFFFFFFu;
            if (u - wlo < (1u << 19)) atomicAdd(&g_fine[u - wlo], 1u);
        }
        gbar(&svar[2]);
    }

    // ============ P4a: reduce 2^20 bins -> 1024 supers (warp per super) ====
    {
        int w = blockIdx.x * (NTHR / 32) + (tid >> 5);
        int lane = tid & 31;
        if (w < NSUP) {
            const uint4* p = (const uint4*)(g_fine + (unsigned)w * 1024u);
            unsigned s = 0;
            #pragma unroll
            for (int j = 0; j < 8; j++) {
                uint4 q = p[lane + 32 * j];
                s += q.x + q.y + q.z + q.w;
            }
            #pragma unroll
            for (int off = 16; off > 0; off >>= 1)
                s += __shfl_down_sync(0xFFFFFFFFu, s, off);
            if (lane == 0) g_super[w] = s;
        }
    }
    gbar(&svar[2]);   // ---- barrier

    // ============ P4b: block0 resolves exact threshold bits ================
    if (blockIdx.x == 0) final_scan(scratch, svar);
    gbar(&svar[2]);   // ---- barrier

    // ============ P5: fixup (normal) or full re-mask (fallback) ============
    const unsigned tb = g_tbits;
    if (!mode) {
        for (unsigned j = (unsigned)gtid; j < cnt; j += NTOT) {
            uint2 e = g_list[j];
            if ((e.y & 0x7FFFFFFFu) >= tb) outs[e.x] = __uint_as_float(e.y);
        }
    } else {
        for (int i = gtid; i < n4; i += NTOT) {
            float4 v = x[i];
            v.x = ((__float_as_uint(v.x) & 0x7FFFFFFFu) >= tb) ? v.x : 0.0f;
            v.y = ((__float_as_uint(v.y) & 0x7FFFFFFFu) >= tb) ? v.y : 0.0f;
            v.z = ((__float_as_uint(v.z) & 0x7FFFFFFFu) >= tb) ? v.z : 0.0f;
            v.w = ((__float_as_uint(v.w) & 0x7FFFFFFFu) >= tb) ? v.w : 0.0f;
            out[i] = v;
        }
        for (int g = gtid; g < rem; g += NTOT) {
            float f = xs[n4 * 4 + g];
            outs[n4 * 4 + g] = ((__float_as_uint(f) & 0x7FFFFFFFu) >= tb) ? f : 0.0f;
        }
    }
}

__global__ void copy_all(const float4* __restrict__ x, float4* __restrict__ out, int n4) {
    int idx = blockIdx.x * blockDim.x + threadIdx.x;
    int stride = gridDim.x * blockDim.x;
    for (int i = idx; i < n4; i += stride) out[i] = x[i];
}

extern "C" void kernel_launch(void* const* d_in, const int* in_sizes, int n_in,
                              void* d_out, int out_size) {
    const float* x = (const float*)d_in[0];
    float* out = (float*)d_out;
    int n = in_sizes[0];

    // k = max(1, int(n * (1.0/e))) — bit-exact replication of the Python.
    const double FRACTION = 1.0 / 2.718281828459045235360287;
    long long kll = (long long)((double)n * FRACTION);
    if (kll < 1) kll = 1;

    int n4 = n >> 2;
    int rem = n & 3;

    if (kll >= (long long)n) {
        copy_all<<<1024, 256>>>((const float4*)x, (float4*)out, n4);
        return;
    }

    zero_all<<<NBLK, NTHR>>>();
    boltzmann_all<<<NBLK, NTHR>>>((const float4*)x, (float4*)out,
                                  n4, rem, (unsigned)kll);
}